// round 11
// baseline (speedup 1.0000x reference)
#include <cuda_runtime.h>
#include <cstdint>

#define VOCAB 50000
#define EMB   32
#define HID   64
#define H4    256
#define NCLS  3
#define BSZ   512
#define TLEN  512

// strided smem layouts (bank-conflict-free, see analysis)
#define ZS_G  72    // z gate-group stride (floats)
#define ZS_S  296   // z batch stride = 4*72 + 8
#define HS_S  72    // h batch stride
#define HS_B  144   // h buffer stride = 2*72

// 51.2MB scratch: precomputed emb @ Wk + bias, per vocab entry (256 floats each)
__device__ float g_table[(size_t)VOCAB * H4];

// ---------- packed f32x2 helpers (sm_103a FFMA2 path, PTX-only) ----------
__device__ __forceinline__ unsigned long long pack2(float lo, float hi) {
    unsigned long long r;
    asm("mov.b64 %0, {%1, %2};" : "=l"(r) : "f"(lo), "f"(hi));
    return r;
}
__device__ __forceinline__ float2 unpack2(unsigned long long v) {
    float2 f;
    asm("mov.b64 {%0, %1}, %2;" : "=f"(f.x), "=f"(f.y) : "l"(v));
    return f;
}
#define FMA2(acc, a, b) \
    asm("fma.rn.f32x2 %0, %1, %2, %0;" : "+l"(acc) : "l"(a), "l"(b))
#define ADD2(d, a, b) \
    asm("add.rn.f32x2 %0, %1, %2;" : "=l"(d) : "l"(a), "l"(b))

__device__ __forceinline__ float ex2a(float x) {
    float r;
    asm("ex2.approx.ftz.f32 %0, %1;" : "=f"(r) : "f"(x));
    return r;
}
__device__ __forceinline__ float rcpa(float x) {
    float r;
    asm("rcp.approx.ftz.f32 %0, %1;" : "=f"(r) : "f"(x));
    return r;
}
#define LOG2E  1.4426950408889634f
#define LOG2E2 2.8853900817779268f

// ---------- kernel 1: g_table[v][j] = sum_e emb[v][e]*Wk[e][j] + b[j] ----------
// 2 columns per thread, STG.64 stores (R9, kept).
__global__ __launch_bounds__(256) void table_kernel(
    const float* __restrict__ emb, const float* __restrict__ Wk,
    const float* __restrict__ bias)
{
    __shared__ __align__(16) float sh_e[64 * EMB];
    const int tid = threadIdx.x;
    const int c0  = (tid & 127) * 2;
    const int rg  = tid >> 7;
    const int v0  = blockIdx.x * 64;

    unsigned long long wkA[16], wkB[16];
#pragma unroll
    for (int m = 0; m < 16; m++) {
        wkA[m] = pack2(Wk[(2 * m) * H4 + c0],     Wk[(2 * m + 1) * H4 + c0]);
        wkB[m] = pack2(Wk[(2 * m) * H4 + c0 + 1], Wk[(2 * m + 1) * H4 + c0 + 1]);
    }
    const float bA = bias[c0], bB = bias[c0 + 1];

    const int nrows = min(64, VOCAB - v0);
    const float4* src = reinterpret_cast<const float4*>(emb + (size_t)v0 * EMB);
    float4* dst = reinterpret_cast<float4*>(sh_e);
    for (int i = tid; i < nrows * (EMB / 4); i += 256) dst[i] = src[i];
    __syncthreads();

    const int r_lo = rg * 32;
    const int r_hi = min(r_lo + 32, nrows);
    for (int r = r_lo; r < r_hi; r++) {
        const ulonglong2* ev = reinterpret_cast<const ulonglong2*>(sh_e + r * EMB);
        unsigned long long a0 = 0ull, a1 = 0ull, b0 = 0ull, b1 = 0ull;
#pragma unroll
        for (int m = 0; m < 8; m++) {
            ulonglong2 p = ev[m];
            FMA2(a0, p.x, wkA[2 * m]);
            FMA2(a1, p.y, wkA[2 * m + 1]);
            FMA2(b0, p.x, wkB[2 * m]);
            FMA2(b1, p.y, wkB[2 * m + 1]);
        }
        unsigned long long sa, sb;
        ADD2(sa, a0, a1);
        ADD2(sb, b0, b1);
        float2 fa = unpack2(sa), fb = unpack2(sb);
        float2 o;
        o.x = bA + fa.x + fa.y;
        o.y = bB + fb.x + fb.y;
        *reinterpret_cast<float2*>(&g_table[(size_t)(v0 + r) * H4 + c0]) = o;
    }
}

// ---------- kernel 2: recurrent LSTM, 2 batch rows per CTA, occ 2 ----------
// Warp-local gate ownership: warp w owns units 8w..8w+7; lane l computes
// column jcol = (l&3)*64 + (8w + (l>>2)) for both batches. z goes through
// warp-private smem (strided, conflict-free); gates read it after a mere
// __syncwarp. Lanes 0-15 gate (s=l>>3, u=8w+(l&7)) and publish h. ONE
// CTA barrier per step (h visibility). Fused-rcp gates; double-buffered h;
// odd-CTA anti-phase stagger.
__global__ __launch_bounds__(256, 2) void lstm_kernel(
    const int*   __restrict__ tokens,
    const float* __restrict__ Wr,
    const float* __restrict__ Wd,
    const float* __restrict__ bd,
    float*       __restrict__ out)
{
    __shared__ __align__(16) float sh_h[2 * HS_B];   // [buf][batch(72)][unit]
    __shared__ float sh_z[2 * ZS_S];                 // [batch(296)][gate(72)][unit]
    __shared__ int   sh_tok[2][TLEN + 1];
    __shared__ float sh_sink;

    const int j    = threadIdx.x;
    const int w    = j >> 5;
    const int l    = j & 31;
    const int u8   = 8 * w + (l >> 2);   // this thread's z unit
    const int g    = l & 3;              // gate index of its column
    const int jcol = g * 64 + u8;        // owned gate column
    const int b0   = blockIdx.x * 2;

    // gate-lane mapping (lanes 0-15)
    const bool gl = (l < 16);
    const int  gs = l >> 3;              // gate batch
    const int  gu = 8 * w + (l & 7);     // gate unit
    float* zrd = sh_z + gs * ZS_S + gu;  // gate-lane z read base

    // stage this CTA's 2 token rows (+1 pad so prefetch needs no clamp)
    for (int i = j; i < 2 * TLEN; i += 256) {
        int s = i >> 9, t = i & (TLEN - 1);
        sh_tok[s][t] = tokens[(size_t)(b0 + s) * TLEN + t];
    }
    if (j < 2) sh_tok[j][TLEN] = tokens[(size_t)(b0 + j) * TLEN + (TLEN - 1)];

    // Wr column jcol, packed over k
    unsigned long long wr2[32];
#pragma unroll
    for (int m = 0; m < 32; m++)
        wr2[m] = pack2(Wr[(2 * m) * H4 + jcol], Wr[(2 * m + 1) * H4 + jcol]);

    if (gl) sh_h[0 * HS_B + gs * HS_S + gu] = 0.0f;
    float cst = 0.0f;  // cell state for (gs, gu) in gate lanes

    // anti-phase stagger: odd CTAs burn ~700 cyc (R6 win, kept)
    if (blockIdx.x & 1) {
        float d = (float)(sh_tok[0][0] & 1);
        const float z0c = 0.0f;
#pragma unroll 1
        for (int i = 0; i < 128; i++)
            asm("add.f32 %0, %0, %1;" : "+f"(d) : "f"(z0c));
        if (d > 2.0f) sh_sink = d;  // never true; keeps chain alive
    }
    __syncthreads();

    // prefetch xz for t=0 (table is L2-resident)
    float xzn0 = g_table[(size_t)sh_tok[0][0] * H4 + jcol];
    float xzn1 = g_table[(size_t)sh_tok[1][0] * H4 + jcol];

    float* zwr = sh_z + g * ZS_G + u8;   // z write base (batch via +ZS_S)

#pragma unroll 1
    for (int t = 0; t < TLEN; t++) {
        const float xz0 = xzn0, xz1 = xzn1;
        xzn0 = g_table[(size_t)sh_tok[0][t + 1] * H4 + jcol];
        xzn1 = g_table[(size_t)sh_tok[1][t + 1] * H4 + jcol];

        // z[s][jcol] = xz[s] + h[s] . Wr[:,jcol]  (xz folded into acc init)
        const float* hb = sh_h + (t & 1) * HS_B;
        const ulonglong2* h0 = reinterpret_cast<const ulonglong2*>(hb);
        const ulonglong2* h1 = reinterpret_cast<const ulonglong2*>(hb + HS_S);
        unsigned long long a0 = pack2(xz0, 0.0f), a1 = 0ull, a2 = 0ull, a3 = 0ull;
        unsigned long long c0 = pack2(xz1, 0.0f), c1 = 0ull, c2 = 0ull, c3 = 0ull;
#pragma unroll
        for (int m = 0; m < 8; m++) {
            ulonglong2 p0 = h0[2 * m];
            ulonglong2 q0 = h0[2 * m + 1];
            ulonglong2 p1 = h1[2 * m];
            ulonglong2 q1 = h1[2 * m + 1];
            const unsigned long long w0 = wr2[4 * m + 0];
            const unsigned long long w1 = wr2[4 * m + 1];
            const unsigned long long w2 = wr2[4 * m + 2];
            const unsigned long long w3 = wr2[4 * m + 3];
            FMA2(a0, p0.x, w0);
            FMA2(a1, p0.y, w1);
            FMA2(a2, q0.x, w2);
            FMA2(a3, q0.y, w3);
            FMA2(c0, p1.x, w0);
            FMA2(c1, p1.y, w1);
            FMA2(c2, q1.x, w2);
            FMA2(c3, q1.y, w3);
        }
        {
            unsigned long long r0, r1;
            float2 f;
            ADD2(r0, a0, a1);
            ADD2(r1, a2, a3);
            ADD2(r0, r0, r1);
            f = unpack2(r0);
            zwr[0] = f.x + f.y;
            ADD2(r0, c0, c1);
            ADD2(r1, c2, c3);
            ADD2(r0, r0, r1);
            f = unpack2(r0);
            zwr[ZS_S] = f.x + f.y;
        }
        __syncwarp();   // z of this warp's units complete (warp-private)

        // gate lanes: fused-rcp form (5 EX2 + 3 RCP)
        if (gl) {
            const float zi = zrd[0 * ZS_G];
            const float zf = zrd[1 * ZS_G];
            const float zg = zrd[2 * ZS_G];
            const float zo = zrd[3 * ZS_G];
            const float ei = ex2a(-LOG2E * zi);
            const float ef = ex2a(-LOG2E * zf);
            const float eg = ex2a(-LOG2E2 * zg);
            const float eo = ex2a(-LOG2E * zo);
            const float fg = rcpa(1.0f + ef);
            const float r1 = rcpa((1.0f + ei) * (1.0f + eg));
            cst = fmaf(fg, cst, (1.0f - eg) * r1);
            const float ec = ex2a(-LOG2E2 * cst);
            const float r2 = rcpa((1.0f + eo) * (1.0f + ec));
            sh_h[((t & 1) ^ 1) * HS_B + gs * HS_S + gu] = (1.0f - ec) * r2;
        }
        __syncthreads();  // single CTA barrier: h published to all warps
    }

    // final h in buffer 0 (last write at t=511 targets (511&1)^1 = 0)
    if (j < 2) {
        const int s = j;
        const float* hrow = sh_h + 0 * HS_B + s * HS_S;
        float l0 = bd[0], l1 = bd[1], l2 = bd[2];
#pragma unroll 8
        for (int uu = 0; uu < HID; uu++) {
            const float h = hrow[uu];
            l0 += h * Wd[uu * NCLS + 0];
            l1 += h * Wd[uu * NCLS + 1];
            l2 += h * Wd[uu * NCLS + 2];
        }
        const float m  = fmaxf(l0, fmaxf(l1, l2));
        const float e0 = ex2a(LOG2E * (l0 - m));
        const float e1 = ex2a(LOG2E * (l1 - m));
        const float e2 = ex2a(LOG2E * (l2 - m));
        const float inv = rcpa(e0 + e1 + e2);
        float* o = out + (size_t)(b0 + s) * NCLS;
        o[0] = e0 * inv;
        o[1] = e1 * inv;
        o[2] = e2 * inv;
    }
}

extern "C" void kernel_launch(void* const* d_in, const int* in_sizes, int n_in,
                              void* d_out, int out_size)
{
    const int*   tokens = (const int*)  d_in[0];
    const float* emb    = (const float*)d_in[1];
    const float* Wk     = (const float*)d_in[2];
    const float* Wr     = (const float*)d_in[3];
    const float* b      = (const float*)d_in[4];
    const float* Wd     = (const float*)d_in[5];
    const float* bd     = (const float*)d_in[6];
    float* out = (float*)d_out;

    table_kernel<<<(VOCAB + 63) / 64, 256>>>(emb, Wk, b);
    lstm_kernel<<<BSZ / 2, 256>>>(tokens, Wr, Wd, bd, out);
}

// round 12
// speedup vs baseline: 1.2245x; 1.2245x over previous
#include <cuda_runtime.h>
#include <cstdint>

#define VOCAB 50000
#define EMB   32
#define HID   64
#define H4    256
#define NCLS  3
#define BSZ   512
#define TLEN  512
#define FULL  0xffffffffu

// h smem layout: batch stride 80 floats (STS banks disjoint), buffer stride 160
#define HS_S  80
#define HS_B  160

// 51.2MB scratch: precomputed emb @ Wk + bias, per vocab entry (256 floats each)
__device__ float g_table[(size_t)VOCAB * H4];

// ---------- packed f32x2 helpers (sm_103a FFMA2 path, PTX-only) ----------
__device__ __forceinline__ unsigned long long pack2(float lo, float hi) {
    unsigned long long r;
    asm("mov.b64 %0, {%1, %2};" : "=l"(r) : "f"(lo), "f"(hi));
    return r;
}
__device__ __forceinline__ float2 unpack2(unsigned long long v) {
    float2 f;
    asm("mov.b64 {%0, %1}, %2;" : "=f"(f.x), "=f"(f.y) : "l"(v));
    return f;
}
#define FMA2(acc, a, b) \
    asm("fma.rn.f32x2 %0, %1, %2, %0;" : "+l"(acc) : "l"(a), "l"(b))
#define ADD2(d, a, b) \
    asm("add.rn.f32x2 %0, %1, %2;" : "=l"(d) : "l"(a), "l"(b))

__device__ __forceinline__ float ex2a(float x) {
    float r;
    asm("ex2.approx.ftz.f32 %0, %1;" : "=f"(r) : "f"(x));
    return r;
}
__device__ __forceinline__ float rcpa(float x) {
    float r;
    asm("rcp.approx.ftz.f32 %0, %1;" : "=f"(r) : "f"(x));
    return r;
}
#define LOG2E  1.4426950408889634f
#define LOG2E2 2.8853900817779268f

// ---------- kernel 1: g_table[v][j] = sum_e emb[v][e]*Wk[e][j] + b[j] ----------
// 2 columns per thread, STG.64 stores (R9, kept).
__global__ __launch_bounds__(256) void table_kernel(
    const float* __restrict__ emb, const float* __restrict__ Wk,
    const float* __restrict__ bias)
{
    __shared__ __align__(16) float sh_e[64 * EMB];
    const int tid = threadIdx.x;
    const int c0  = (tid & 127) * 2;
    const int rg  = tid >> 7;
    const int v0  = blockIdx.x * 64;

    unsigned long long wkA[16], wkB[16];
#pragma unroll
    for (int m = 0; m < 16; m++) {
        wkA[m] = pack2(Wk[(2 * m) * H4 + c0],     Wk[(2 * m + 1) * H4 + c0]);
        wkB[m] = pack2(Wk[(2 * m) * H4 + c0 + 1], Wk[(2 * m + 1) * H4 + c0 + 1]);
    }
    const float bA = bias[c0], bB = bias[c0 + 1];

    const int nrows = min(64, VOCAB - v0);
    const float4* src = reinterpret_cast<const float4*>(emb + (size_t)v0 * EMB);
    float4* dst = reinterpret_cast<float4*>(sh_e);
    for (int i = tid; i < nrows * (EMB / 4); i += 256) dst[i] = src[i];
    __syncthreads();

    const int r_lo = rg * 32;
    const int r_hi = min(r_lo + 32, nrows);
    for (int r = r_lo; r < r_hi; r++) {
        const ulonglong2* ev = reinterpret_cast<const ulonglong2*>(sh_e + r * EMB);
        unsigned long long a0 = 0ull, a1 = 0ull, b0 = 0ull, b1 = 0ull;
#pragma unroll
        for (int m = 0; m < 8; m++) {
            ulonglong2 p = ev[m];
            FMA2(a0, p.x, wkA[2 * m]);
            FMA2(a1, p.y, wkA[2 * m + 1]);
            FMA2(b0, p.x, wkB[2 * m]);
            FMA2(b1, p.y, wkB[2 * m + 1]);
        }
        unsigned long long sa, sb;
        ADD2(sa, a0, a1);
        ADD2(sb, b0, b1);
        float2 fa = unpack2(sa), fb = unpack2(sb);
        float2 o;
        o.x = bA + fa.x + fa.y;
        o.y = bB + fb.x + fb.y;
        *reinterpret_cast<float2*>(&g_table[(size_t)(v0 + r) * H4 + c0]) = o;
    }
}

// ---------- kernel 2: recurrent LSTM, 2 batch rows per CTA, occ 2 ----------
// Gate-split pair ownership, 128 threads. Lane pair (2u, 2u+1) owns unit u:
//   even lane: cols i (u)    and g (u+128), both batches
//   odd  lane: cols f (u+64) and o (u+192), both batches
// After the dot each lane holds 4 complete z's; ONE shfl.bfly.b64 swaps the
// cross-batch halves so even gates batch0, odd gates batch1 -- fully in
// registers, NO z smem. Every lane gates + STSes one h float. ONE CTA
// barrier per step. Double-buffered h; fused-rcp gates; anti-phase stagger.
__global__ __launch_bounds__(128, 2) void lstm_kernel(
    const int*   __restrict__ tokens,
    const float* __restrict__ Wr,
    const float* __restrict__ Wd,
    const float* __restrict__ bd,
    float*       __restrict__ out)
{
    __shared__ __align__(16) float sh_h[2 * HS_B];   // [buf(160)][batch(80)][unit]
    __shared__ int   sh_tok[2][TLEN + 1];
    __shared__ float sh_sink;

    const int j   = threadIdx.x;          // 0..127
    const int u   = j >> 1;               // unit 0..63
    const int par = j & 1;                // 0: i/g cols, gates batch0; 1: f/o, batch1
    const int cA  = u + par * 64;         // i (even) / f (odd)
    const int cB  = u + 128 + par * 64;   // g (even) / o (odd)
    const int b0  = blockIdx.x * 2;

    // stage this CTA's 2 token rows (+1 pad so prefetch needs no clamp)
    for (int i = j; i < 2 * TLEN; i += 128) {
        int s = i >> 9, t = i & (TLEN - 1);
        sh_tok[s][t] = tokens[(size_t)(b0 + s) * TLEN + t];
    }
    if (j < 2) sh_tok[j][TLEN] = tokens[(size_t)(b0 + j) * TLEN + (TLEN - 1)];

    // Wr columns cA, cB packed over k (64 b64 = 128 regs)
    unsigned long long wA[32], wB[32];
#pragma unroll
    for (int m = 0; m < 32; m++) {
        wA[m] = pack2(Wr[(2 * m) * H4 + cA], Wr[(2 * m + 1) * H4 + cA]);
        wB[m] = pack2(Wr[(2 * m) * H4 + cB], Wr[(2 * m + 1) * H4 + cB]);
    }

    sh_h[0 * HS_B + par * HS_S + u] = 0.0f;  // 128 threads cover [2][64]
    float cst = 0.0f;                        // cell state for (par, u)

    // anti-phase stagger: odd CTAs burn ~700 cyc (R6 win, kept)
    if (blockIdx.x & 1) {
        float d = (float)(sh_tok[0][0] & 1);
        const float z0c = 0.0f;
#pragma unroll 1
        for (int i = 0; i < 128; i++)
            asm("add.f32 %0, %0, %1;" : "+f"(d) : "f"(z0c));
        if (d > 2.0f) sh_sink = d;  // never true; keeps chain alive
    }
    __syncthreads();

    // prefetch xz for t=0: cols cA, cB for both batches
    float xzA0 = g_table[(size_t)sh_tok[0][0] * H4 + cA];
    float xzB0 = g_table[(size_t)sh_tok[0][0] * H4 + cB];
    float xzA1 = g_table[(size_t)sh_tok[1][0] * H4 + cA];
    float xzB1 = g_table[(size_t)sh_tok[1][0] * H4 + cB];

#pragma unroll 1
    for (int t = 0; t < TLEN; t++) {
        const float iA0 = xzA0, iB0 = xzB0, iA1 = xzA1, iB1 = xzB1;
        const int tk0 = sh_tok[0][t + 1], tk1 = sh_tok[1][t + 1];
        xzA0 = g_table[(size_t)tk0 * H4 + cA];
        xzB0 = g_table[(size_t)tk0 * H4 + cB];
        xzA1 = g_table[(size_t)tk1 * H4 + cA];
        xzB1 = g_table[(size_t)tk1 * H4 + cB];

        const float* hb = sh_h + (t & 1) * HS_B;
        const ulonglong2* h0 = reinterpret_cast<const ulonglong2*>(hb);
        const ulonglong2* h1 = reinterpret_cast<const ulonglong2*>(hb + HS_S);

        // 4 column dots (2 cols x 2 batches), xz folded into acc init
        unsigned long long aA0 = pack2(iA0, 0.0f), aA1 = 0ull;
        unsigned long long aB0 = pack2(iB0, 0.0f), aB1 = 0ull;
        unsigned long long cA0 = pack2(iA1, 0.0f), cA1 = 0ull;
        unsigned long long cB0 = pack2(iB1, 0.0f), cB1 = 0ull;
#pragma unroll
        for (int m = 0; m < 16; m++) {
            ulonglong2 p0 = h0[m];
            ulonglong2 p1 = h1[m];
            const unsigned long long w0 = wA[2 * m], w1 = wA[2 * m + 1];
            const unsigned long long v0 = wB[2 * m], v1 = wB[2 * m + 1];
            FMA2(aA0, p0.x, w0);
            FMA2(aA1, p0.y, w1);
            FMA2(aB0, p0.x, v0);
            FMA2(aB1, p0.y, v1);
            FMA2(cA0, p1.x, w0);
            FMA2(cA1, p1.y, w1);
            FMA2(cB0, p1.x, v0);
            FMA2(cB1, p1.y, v1);
        }
        float zA0, zB0, zA1, zB1;
        {
            unsigned long long r;
            float2 f;
            ADD2(r, aA0, aA1); f = unpack2(r); zA0 = f.x + f.y;
            ADD2(r, aB0, aB1); f = unpack2(r); zB0 = f.x + f.y;
            ADD2(r, cA0, cA1); f = unpack2(r); zA1 = f.x + f.y;
            ADD2(r, cB0, cB1); f = unpack2(r); zB1 = f.x + f.y;
        }

        // pair exchange: even sends its batch1 pair, odd sends its batch0 pair
        const unsigned long long send = par ? pack2(zA0, zB0) : pack2(zA1, zB1);
        const unsigned long long recv = __shfl_xor_sync(FULL, send, 1);
        const float2 rv = unpack2(recv);

        // even lane: zi=zA0, zg=zB0, zf=rv.x, zo=rv.y   (batch 0)
        // odd  lane: zf=zA1, zo=zB1, zi=rv.x, zg=rv.y   (batch 1)
        const float zi = par ? rv.x : zA0;
        const float zg = par ? rv.y : zB0;
        const float zf = par ? zA1 : rv.x;
        const float zo = par ? zB1 : rv.y;

        // fused-rcp gates (5 EX2 + 3 RCP)
        const float ei = ex2a(-LOG2E * zi);
        const float ef = ex2a(-LOG2E * zf);
        const float eg = ex2a(-LOG2E2 * zg);
        const float eo = ex2a(-LOG2E * zo);
        const float fg = rcpa(1.0f + ef);
        const float r1 = rcpa((1.0f + ei) * (1.0f + eg));
        cst = fmaf(fg, cst, (1.0f - eg) * r1);
        const float ec = ex2a(-LOG2E2 * cst);
        const float r2 = rcpa((1.0f + eo) * (1.0f + ec));
        sh_h[((t & 1) ^ 1) * HS_B + par * HS_S + u] = (1.0f - ec) * r2;

        __syncthreads();  // single barrier: h published, buffers swap
    }

    // final h in buffer 0 (last write at t=511 targets (511&1)^1 = 0)
    if (j < 2) {
        const int s = j;
        const float* hrow = sh_h + s * HS_S;
        float l0 = bd[0], l1 = bd[1], l2 = bd[2];
#pragma unroll 8
        for (int uu = 0; uu < HID; uu++) {
            const float h = hrow[uu];
            l0 += h * Wd[uu * NCLS + 0];
            l1 += h * Wd[uu * NCLS + 1];
            l2 += h * Wd[uu * NCLS + 2];
        }
        const float m  = fmaxf(l0, fmaxf(l1, l2));
        const float e0 = ex2a(LOG2E * (l0 - m));
        const float e1 = ex2a(LOG2E * (l1 - m));
        const float e2 = ex2a(LOG2E * (l2 - m));
        const float inv = rcpa(e0 + e1 + e2);
        float* o = out + (size_t)(b0 + s) * NCLS;
        o[0] = e0 * inv;
        o[1] = e1 * inv;
        o[2] = e2 * inv;
    }
}

extern "C" void kernel_launch(void* const* d_in, const int* in_sizes, int n_in,
                              void* d_out, int out_size)
{
    const int*   tokens = (const int*)  d_in[0];
    const float* emb    = (const float*)d_in[1];
    const float* Wk     = (const float*)d_in[2];
    const float* Wr     = (const float*)d_in[3];
    const float* b      = (const float*)d_in[4];
    const float* Wd     = (const float*)d_in[5];
    const float* bd     = (const float*)d_in[6];
    float* out = (float*)d_out;

    table_kernel<<<(VOCAB + 63) / 64, 256>>>(emb, Wk, b);
    lstm_kernel<<<BSZ / 2, 128>>>(tokens, Wr, Wd, bd, out);
}